// round 17
// baseline (speedup 1.0000x reference)
#include <cuda_runtime.h>
#include <cuda_bf16.h>

// MultiTaskLoss: B=64 samples, 512x512, scalar loss output.
// R17 (= R16 fixed): accumulator reset loop now covers all BN*8=512 entries
//      (R16's `if (t < 512)` with 256 threads left half un-reset, corrupting
//      graph replays). maskdxh 16 px/thread (MLP=4); main 128-thread blocks
//      with PRMT byte extraction.

#define BN 64
#define HH 512
#define WW 512
#define NPIX (HH * WW)
#define MAIN_TPB 128
#define MAIN_GRID (BN * NPIX / 16 / MAIN_TPB)
#define PROWS (HH + 20)      // 10 pad rows top/bottom

__device__ unsigned long long g_dxh[BN * PROWS * WW / 8];   // horiz d^2, u8x8
__device__ float              g_acc[BN * 8];
__device__ unsigned           g_done;

// ---------------------------------------------------------------------------
__device__ __forceinline__ float frcp_approx(float w) {
    float r;
    asm("rcp.approx.f32 %0, %1;" : "=f"(r) : "f"(w));
    return r;
}

// nearest-set-bit distance^2 (clamped 101) from center (bit 10) of 21-bit window
__device__ __forceinline__ int win_d2(unsigned win) {
    unsigned lo = win & 0x7FFu;            // bits 0..10 (left side, center incl)
    unsigned hi = win >> 10;               // bits 0..10 (right side, center incl)
    int dl = __clz(lo) - 21;               // lo==0 -> 11 (no guard needed)
    int dh = __clz(__brev(hi));            // lowest set bit idx; hi==0 -> 32
    int d  = min(min(dl, dh), 11);
    return min(d * d, 101);
}

// ---------------------------------------------------------------------------
// Fused: build 8 row-masks in smem via ballots, then emit horizontal d^2 (u8).
// grid (65, 64), 256 threads, 16 px/thread: blockIdx.x==64 -> pads + init.
__global__ void __launch_bounds__(256) maskdxh_kernel(const float4* __restrict__ targets4) {
    int b = blockIdx.y;
    int t = threadIdx.x;

    if (blockIdx.x == 64) {
        for (int i = t; i < 20 * 64; i += 256) {
            int r = i >> 6;
            int row = (r < 10) ? r : r + 512;   // 0..9 and 522..531
            g_dxh[(b * PROWS + row) * 64 + (i & 63)] = 0x6565656565656565ull;
        }
        if (b == 0) {
            for (int i = t; i < BN * 8; i += 256) g_acc[i] = 0.0f;  // ALL 512
            if (t == 0) g_done = 0u;
        }
        return;
    }

    __shared__ unsigned smask[8][18];   // 8 rows, 16 words + 1 pad each side

    int y0 = blockIdx.x * 8;            // first of 8 rows this block owns

    if (t < 144) ((unsigned*)smask)[t] = 0u;
    __syncthreads();

    // --- 4 upfront float4 loads (MLP=4), 16 px/thread ---
    int g4 = ((b * NPIX + y0 * WW) >> 2) + t * 4;
    float4 v0 = targets4[g4 + 0];
    float4 v1 = targets4[g4 + 1];
    float4 v2 = targets4[g4 + 2];
    float4 v3 = targets4[g4 + 3];
    unsigned m =
          (v0.x > 0.5f ? 0x0001u : 0u) | (v0.y > 0.5f ? 0x0002u : 0u)
        | (v0.z > 0.5f ? 0x0004u : 0u) | (v0.w > 0.5f ? 0x0008u : 0u)
        | (v1.x > 0.5f ? 0x0010u : 0u) | (v1.y > 0.5f ? 0x0020u : 0u)
        | (v1.z > 0.5f ? 0x0040u : 0u) | (v1.w > 0.5f ? 0x0080u : 0u)
        | (v2.x > 0.5f ? 0x0100u : 0u) | (v2.y > 0.5f ? 0x0200u : 0u)
        | (v2.z > 0.5f ? 0x0400u : 0u) | (v2.w > 0.5f ? 0x0800u : 0u)
        | (v3.x > 0.5f ? 0x1000u : 0u) | (v3.y > 0.5f ? 0x2000u : 0u)
        | (v3.z > 0.5f ? 0x4000u : 0u) | (v3.w > 0.5f ? 0x8000u : 0u);

    unsigned lane  = t & 31;
    unsigned gmask = 0x3u << (lane & ~1u);          // lane pair = 32 px
    unsigned word  = __reduce_or_sync(gmask, m << ((lane & 1) * 16));
    if ((lane & 1) == 0) {
        int p0 = t * 16;
        smask[p0 >> 9][1 + ((p0 & 511) >> 5)] = word;
    }
    __syncthreads();

    // --- horizontal d^2, 16 px/thread (2 u64 outputs) ---
    int r  = t >> 5;                    // row within strip (32 thr/row)
    int x0 = (t & 31) << 4;             // first pixel in row
    const unsigned* rowp = &smask[r][0];
    unsigned long long ob = (unsigned long long)(b * PROWS + 10 + y0 + r) * 64;
    #pragma unroll
    for (int k = 0; k < 2; ++k) {
        int sx = x0 + k * 8 - 10;
        const unsigned* rp = rowp + 1 + (sx >> 5);
        unsigned long long w =
            (((unsigned long long)rp[1] << 32) | rp[0]) >> (sx & 31);
        unsigned long long o = 0ull;
        #pragma unroll
        for (int j = 0; j < 8; ++j) {
            unsigned win = (unsigned)(w >> j) & 0x1FFFFFu;
            o |= (unsigned long long)win_d2(win) << (8 * j);
        }
        g_dxh[ob + (x0 >> 3) + k] = o;
    }
}

// ---------------------------------------------------------------------------
__global__ void __launch_bounds__(MAIN_TPB) main_kernel(
    const float4* __restrict__ preds4,
    const int*    __restrict__ task_ids,
    float*        __restrict__ out)
{
    __shared__ float sTab[102];
    if (threadIdx.x < 102) sTab[threadIdx.x] = fminf(sqrtf((float)threadIdx.x), 10.0f);

    int q = blockIdx.x * MAIN_TPB + threadIdx.x;     // 16-px strip index
    int b  = q >> 14;                                // 16384 strips per sample
    int y  = (q >> 5) & 511;
    int xo = q & 31;                                 // 16-px group in row

    // ---- byte-SIMD vertical DT (128-bit loads) ----
    const ulonglong2* bp = (const ulonglong2*)g_dxh + (b * PROWS + 10 + y) * 32 + xo;
    ulonglong2 cur = *bp;
    unsigned bw[4] = {(unsigned)cur.x, (unsigned)(cur.x >> 32),
                      (unsigned)cur.y, (unsigned)(cur.y >> 32)};

    #pragma unroll 1
    for (int ady = 1; ady <= 10; ++ady) {
        int a2 = ady * ady;
        unsigned m4 = __vmaxu4(__vmaxu4(bw[0], bw[1]), __vmaxu4(bw[2], bw[3]));
        m4 = __vmaxu4(m4, m4 >> 16);
        m4 = __vmaxu4(m4, m4 >> 8);
        if (a2 >= (int)(m4 & 0xFFu)) break;
        ulonglong2 up = bp[-(ady * 32)];
        ulonglong2 dn = bp[  ady * 32 ];
        unsigned a2b = a2 * 0x01010101u;   // per-byte add, sums < 256: no carry
        bw[0] = __vminu4(bw[0], __vminu4((unsigned)up.x,         (unsigned)dn.x)         + a2b);
        bw[1] = __vminu4(bw[1], __vminu4((unsigned)(up.x >> 32), (unsigned)(dn.x >> 32)) + a2b);
        bw[2] = __vminu4(bw[2], __vminu4((unsigned)up.y,         (unsigned)dn.y)         + a2b);
        bw[3] = __vminu4(bw[3], __vminu4((unsigned)(up.y >> 32), (unsigned)(dn.y >> 32)) + a2b);
    }

    // preds loads after the DT loop (shorter live range)
    float4 xv[4];
    #pragma unroll
    for (int k = 0; k < 4; ++k) xv[k] = preds4[q * 4 + k];

    __syncthreads();   // sTab ready

    // ---- pointwise math + 6 sums over 16 px ----
    // byte==0 <=> fg. |x| <= ~6: w = 1+exp(-x); p = rcp.approx(w);
    // sp_neg = log(w); sp_pos = x + sp_neg. Sbg = Sall - Sfg in finalize.
    float s2 = (float)(__popc(__vseteq4(bw[0], 0u)) + __popc(__vseteq4(bw[1], 0u))
                     + __popc(__vseteq4(bw[2], 0u)) + __popc(__vseteq4(bw[3], 0u)));
    float s0 = 0.f, s1 = 0.f, s4 = 0.f, s5 = 0.f, sAll = 0.f;
    #pragma unroll
    for (int j = 0; j < 16; ++j) {
        float x_ = ((const float*)xv)[j];
        // single-byte extract: nibble0 picks byte j, nibbles 1-3 pick zeros
        unsigned b2 = __byte_perm(bw[j >> 2], 0u, 0x4440u | (j & 3));
        bool fg = (b2 == 0);

        float e      = __expf(-x_);
        float w      = 1.0f + e;
        float p      = frcp_approx(w);            // sigmoid(x)
        float sp_neg = __logf(w);                 // softplus(-x) = -log(p)
        float spv    = sp_neg + (fg ? 0.0f : x_); // sp_neg (fg) or sp_pos (bg)

        s1 += p;
        s4 = fmaf(sTab[b2], p, s4);
        sAll += spv;
        if (fg) {
            s0 += p;
            s5 += sp_neg;
        }
    }

    // ---- block reduction: warp shuffle -> shared -> per-sample atomics ----
    float vals[6] = {s0, s1, s2, s4, s5, sAll};
    __shared__ float shr[4 * 6];
    int lane = threadIdx.x & 31;
    int wid  = threadIdx.x >> 5;
    #pragma unroll
    for (int qq = 0; qq < 6; ++qq) {
        float v = vals[qq];
        #pragma unroll
        for (int o = 16; o; o >>= 1) v += __shfl_down_sync(0xffffffffu, v, o);
        if (lane == 0) shr[wid * 6 + qq] = v;
    }
    __syncthreads();
    if (threadIdx.x < 6) {
        float ssum = 0.0f;
        #pragma unroll
        for (int w = 0; w < 4; ++w) ssum += shr[w * 6 + threadIdx.x];
        atomicAdd(&g_acc[b * 8 + threadIdx.x], ssum);
    }

    // ---- last block finalizes ----
    __shared__ unsigned sIsLast;
    __threadfence();
    __syncthreads();
    if (threadIdx.x == 0)
        sIsLast = (atomicAdd(&g_done, 1u) == MAIN_GRID - 1) ? 1u : 0u;
    __syncthreads();
    if (sIsLast) {
        __shared__ float shp[64];
        if (threadIdx.x < 64) {
            int bb = threadIdx.x;
            const float Nf   = (float)NPIX;
            const float invN = 1.0f / Nf;
            float* a = &g_acc[bb * 8];
            float Sint = a[0], Spc = a[1], St = a[2];
            float Sbd  = a[3], Sfg = a[4], Sall = a[5];
            float Sbg  = Sall - Sfg;
            float Sbce = Sall;

            float dice = 1.0f - (2.0f * Sint + 1e-5f) / (Spc + St + 1e-5f);
            float base = dice + Sbce * invN;
            float boundary = Sbd * invN;
            float fgw = fminf(fmaxf((Nf - St) / (St + 1e-7f), 1.0f), 10.0f);
            float fgl = (St == 0.0f) ? 0.0f : (fgw * Sfg + Sbg) * invN;

            const float DW[3] = {2.0f, 3.0f, 5.0f};
            const float FW[3] = {1.0f, 1.5f, 3.0f};
            int ti = task_ids[bb];
            shp[bb] = base + DW[ti] * boundary + FW[ti] * fgl;  // BASE_W == 1
        }
        __syncthreads();
        if (threadIdx.x == 0) {
            float ssum = 0.0f;
            #pragma unroll
            for (int i = 0; i < 64; ++i) ssum += shp[i];
            out[0] = ssum * (1.0f / 64.0f);
        }
    }
}

// ---------------------------------------------------------------------------
extern "C" void kernel_launch(void* const* d_in, const int* in_sizes, int n_in,
                              void* d_out, int out_size)
{
    const float* preds = (const float*)d_in[0];
    const float* targs = (const float*)d_in[1];
    const int*   tids  = (const int*)d_in[2];
    float*       out   = (float*)d_out;

    dim3 mg(65, BN);   // 64 row-strips + 1 pad/init column
    maskdxh_kernel<<<mg, 256>>>((const float4*)targs);
    main_kernel<<<MAIN_GRID, MAIN_TPB>>>((const float4*)preds, tids, out);
}